// round 16
// baseline (speedup 1.0000x reference)
#include <cuda_runtime.h>
#include <cuda_fp16.h>

#define Wd 256
#define Hd 256
#define Bd 64
#define NPIX (Bd*Hd*Wd)
#define QIMG 16
#define QPIX (QIMG*Hd*Wd)   // elements per quarter
#define NVQ  (QPIX/4)       // float4 vectors per quarter
#define EPSf 1e-12f

// ---- iteration-invariant scratch (fp32) ----
__device__ __align__(16) float g_g2x[NPIX];
__device__ __align__(16) float g_g2y[NPIX];
__device__ __align__(16) float g_rc [NPIX];
// ---- dual state, fp16 packed per pixel: pa = (p11,p21), pb = (p12,p22) ----
__device__ __align__(16) unsigned g_pa[NPIX];
__device__ __align__(16) unsigned g_pb[NPIX];

union F4 { float4 v; float f[4]; };

__device__ __forceinline__ float4 ld4(const float* p) { return *reinterpret_cast<const float4*>(p); }
__device__ __forceinline__ void   st4(float* p, float4 v) { *reinterpret_cast<float4*>(p) = v; }
__device__ __forceinline__ uint4  ldu4(const unsigned* p) { return *reinterpret_cast<const uint4*>(p); }
__device__ __forceinline__ void   stu4(unsigned* p, uint4 v) { *reinterpret_cast<uint4*>(p) = v; }

__device__ __forceinline__ float2 h2f(unsigned w) {
    __half2 h = *reinterpret_cast<__half2*>(&w);
    return __half22float2(h);
}
__device__ __forceinline__ unsigned f2h(float a, float b) {
    __half2 h = __floats2half2_rn(a, b);
    return *reinterpret_cast<unsigned*>(&h);
}
__device__ __forceinline__ unsigned u4get(const uint4& u, int k) {
    return (k == 0) ? u.x : (k == 1) ? u.y : (k == 2) ? u.z : u.w;
}
__device__ __forceinline__ void u4set(uint4& u, int k, unsigned v) {
    if (k == 0) u.x = v; else if (k == 1) u.y = v; else if (k == 2) u.z = v; else u.w = v;
}

// ============================================================================
// Init (per quarter): g2x, g2y (centered grads of y, x boundary), rc, iter-1 u.
// ============================================================================
__global__ void __launch_bounds__(256) k_init(
    const float* __restrict__ x, const float* __restrict__ y,
    const float* __restrict__ tp, const float* __restrict__ lp,
    float* __restrict__ u1, float* __restrict__ u2, int off)
{
    int v = blockIdx.x * blockDim.x + threadIdx.x;
    if (v >= NVQ) return;
    int il = v << 2;
    int idx = il + off;
    int j4 = il & (Wd - 1);
    int i  = (il >> 8) & (Hd - 1);

    float ts  = tp[0];
    float l_t = lp[0] * ts;

    F4 X, Y, Yu, Yd, Xu, Xd;
    X.v = ld4(x + idx);
    Y.v = ld4(y + idx);
    float yl = (j4 > 0)       ? y[idx - 1] : 0.f;
    float yr = (j4 + 4 < Wd)  ? y[idx + 4] : 0.f;
    Yu.v = (i > 0)      ? ld4(y + idx - Wd) : make_float4(0,0,0,0);
    Yd.v = (i < Hd - 1) ? ld4(y + idx + Wd) : make_float4(0,0,0,0);
    Xd.v = (i == 0)      ? ld4(x + idx + Wd) : make_float4(0,0,0,0);
    Xu.v = (i == Hd - 1) ? ld4(x + idx - Wd) : make_float4(0,0,0,0);

    F4 GX, GY, RC, O1, O2;
#pragma unroll
    for (int k = 0; k < 4; k++) {
        int j = j4 + k;
        float gx;
        if (j == 0)            gx = 0.5f * (X.f[1] - X.f[0]);
        else if (j == Wd - 1)  gx = 0.5f * (X.f[3] - X.f[2]);
        else {
            float yn = (k < 3) ? Y.f[k + 1] : yr;
            float yp = (k > 0) ? Y.f[k - 1] : yl;
            gx = 0.5f * (yn - yp);
        }
        float gy;
        if (i == 0)            gy = 0.5f * (Xd.f[k] - X.f[k]);
        else if (i == Hd - 1)  gy = 0.5f * (X.f[k] - Xu.f[k]);
        else                   gy = 0.5f * (Yd.f[k] - Yu.f[k]);

        float rc = Y.f[k] - X.f[k];
        GX.f[k] = gx; GY.f[k] = gy; RC.f[k] = rc;

        float rho  = rc + EPSf;
        float grad = gx * gx + gy * gy + EPSf;
        float lg   = l_t * grad;
        float v1, v2;
        if      (rho < -lg)   { v1 =  l_t * gx; v2 =  l_t * gy; }
        else if (rho >  lg)   { v1 = -l_t * gx; v2 = -l_t * gy; }
        else if (grad > EPSf) { float s = -rho / grad; v1 = s * gx; v2 = s * gy; }
        else                  { v1 = 0.f; v2 = 0.f; }
        O1.f[k] = v1; O2.f[k] = v2;
    }
    st4(g_g2x + idx, GX.v);
    st4(g_g2y + idx, GY.v);
    st4(g_rc  + idx, RC.v);
    st4(u1 + idx, O1.v);
    st4(u2 + idx, O2.v);
}

// ============================================================================
// P update (per quarter): forward grads of u, dual projection. In-place packed p.
// ============================================================================
template <bool FIRST>
__global__ void __launch_bounds__(256) k_update_p(
    const float* __restrict__ tp, const float* __restrict__ ap,
    const float* __restrict__ u1, const float* __restrict__ u2, int off)
{
    int v = blockIdx.x * blockDim.x + threadIdx.x;
    if (v >= NVQ) return;
    int il = v << 2;
    int idx = il + off;
    int j4 = il & (Wd - 1);
    int i  = (il >> 8) & (Hd - 1);

    float taut = ap[0] / tp[0];

    F4 U1, U2, U1d, U2d;
    U1.v = ld4(u1 + idx);
    U2.v = ld4(u2 + idx);
    float u1r = (j4 + 4 < Wd) ? u1[idx + 4] : 0.f;
    float u2r = (j4 + 4 < Wd) ? u2[idx + 4] : 0.f;
    bool has_down = (i < Hd - 1);
    U1d.v = has_down ? ld4(u1 + idx + Wd) : make_float4(0,0,0,0);
    U2d.v = has_down ? ld4(u2 + idx + Wd) : make_float4(0,0,0,0);

    uint4 PA = make_uint4(0,0,0,0), PB = make_uint4(0,0,0,0);
    if (!FIRST) {
        PA = ldu4(g_pa + idx);
        PB = ldu4(g_pb + idx);
    }

    uint4 OA, OB;
#pragma unroll
    for (int k = 0; k < 4; k++) {
        int j = j4 + k;
        float u1x = (j < Wd - 1) ? ((k < 3) ? U1.f[k + 1] : u1r) - U1.f[k] : 0.f;
        float u2x = (j < Wd - 1) ? ((k < 3) ? U2.f[k + 1] : u2r) - U2.f[k] : 0.f;
        float u1y = has_down ? (U1d.f[k] - U1.f[k]) : 0.f;
        float u2y = has_down ? (U2d.f[k] - U2.f[k]) : 0.f;

        float n1 = sqrtf(u1x * u1x + u1y * u1y + EPSf);
        float n2 = sqrtf(u2x * u2x + u2y * u2y + EPSf);
        float f1 = 1.0f / (1.0f + taut * n1);
        float f2 = 1.0f / (1.0f + taut * n2);

        float p11o = 0.f, p21o = 0.f, p12o = 0.f, p22o = 0.f;
        if (!FIRST) {
            float2 a = h2f(u4get(PA, k));
            float2 b = h2f(u4get(PB, k));
            p11o = a.x; p21o = a.y; p12o = b.x; p22o = b.y;
        }

        float o11 = (p11o + taut * u1x) * f1;
        float o12 = (p12o + taut * u1y) * f1;
        float o21 = (p21o + taut * u2x) * f2;
        float o22 = (p22o + taut * u2y) * f2;
        u4set(OA, k, f2h(o11, o21));
        u4set(OB, k, f2h(o12, o22));
    }
    stu4(g_pa + idx, OA);
    stu4(g_pb + idx, OB);
}

// ============================================================================
// U update (per quarter): thresholding + u = v + ts * div(p). In-place u.
// ============================================================================
__global__ void __launch_bounds__(256) k_update_u(
    const float* __restrict__ tp, const float* __restrict__ lp,
    float* __restrict__ u1, float* __restrict__ u2, int off)
{
    int v = blockIdx.x * blockDim.x + threadIdx.x;
    if (v >= NVQ) return;
    int il = v << 2;
    int idx = il + off;
    int j4 = il & (Wd - 1);
    int i  = (il >> 8) & (Hd - 1);

    float ts  = tp[0];
    float l_t = lp[0] * ts;

    F4 U1, U2, GX, GY, RC;
    U1.v  = ld4(u1 + idx);
    U2.v  = ld4(u2 + idx);
    GX.v  = ld4(g_g2x + idx);
    GY.v  = ld4(g_g2y + idx);
    RC.v  = ld4(g_rc + idx);
    uint4 PA = ldu4(g_pa + idx);   // (p11,p21) x4
    uint4 PB = ldu4(g_pb + idx);   // (p12,p22) x4
    float p11l = 0.f, p21l = 0.f;
    if (j4 > 0) {
        float2 a = h2f(g_pa[idx - 1]);
        p11l = a.x; p21l = a.y;
    }
    bool has_up = (i > 0);
    uint4 PBu = has_up ? ldu4(g_pb + idx - Wd) : make_uint4(0,0,0,0);

    F4 O1, O2;
#pragma unroll
    for (int k = 0; k < 4; k++) {
        int j = j4 + k;
        float2 a  = h2f(u4get(PA, k));    // p11, p21
        float2 b  = h2f(u4get(PB, k));    // p12, p22
        float2 bu = h2f(u4get(PBu, k));   // p12u, p22u

        float lft11, lft21;
        if (k > 0) {
            float2 al = h2f(u4get(PA, k - 1));
            lft11 = al.x; lft21 = al.y;
        } else { lft11 = p11l; lft21 = p21l; }

        float dx1 = (j == 0) ? a.x : (a.x - lft11);
        float dx2 = (j == 0) ? a.y : (a.y - lft21);
        float dy1 = has_up ? (b.x - bu.x) : b.x;
        float dy2 = has_up ? (b.y - bu.y) : b.y;

        float gx = GX.f[k], gy = GY.f[k];
        float rho  = RC.f[k] + gx * U1.f[k] + gy * U2.f[k] + EPSf;
        float grad = gx * gx + gy * gy + EPSf;
        float lg   = l_t * grad;
        float v1, v2;
        if      (rho < -lg)   { v1 =  l_t * gx; v2 =  l_t * gy; }
        else if (rho >  lg)   { v1 = -l_t * gx; v2 = -l_t * gy; }
        else if (grad > EPSf) { float s = -rho / grad; v1 = s * gx; v2 = s * gy; }
        else                  { v1 = 0.f; v2 = 0.f; }

        O1.f[k] = U1.f[k] + v1 + ts * (dx1 + dy1);
        O2.f[k] = U2.f[k] + v2 + ts * (dx2 + dy2);
    }
    st4(u1 + idx, O1.v);
    st4(u2 + idx, O2.v);
}

// ============================================================================
// Host: one quarter-pipeline on a stream; optionally record `mid` at the
// midpoint (after launch #10 of 19) to release a staggered successor.
// ============================================================================
static void run_quarter(cudaStream_t s, int off,
                        const float* x, const float* y,
                        const float* t, const float* l, const float* a,
                        float* u1, float* u2, cudaEvent_t mid)
{
    const int threads = 256;
    const int blocks  = (NVQ + threads - 1) / threads;
    k_init<<<blocks, threads, 0, s>>>(x, y, t, l, u1, u2, off);
    k_update_p<true><<<blocks, threads, 0, s>>>(t, a, u1, u2, off);
    for (int it = 0; it < 9; ++it) {
        k_update_u<<<blocks, threads, 0, s>>>(t, l, u1, u2, off);
        if (it < 8)
            k_update_p<false><<<blocks, threads, 0, s>>>(t, a, u1, u2, off);
        if (it == 3 && mid)             // after 10 launches total
            cudaEventRecord(mid, s);
    }
}

// ============================================================================
// Launch: staggered 4-stream schedule.
//   A(q0), B(q1) start at t=0; C(q2) waits A's midpoint; D(q3) waits B's.
// Critical path ~1.5 pipeline-lengths; concurrent WS <= 3 quarters (84MB)
// except a transient 4-quarter window.
// ============================================================================
extern "C" void kernel_launch(void* const* d_in, const int* in_sizes, int n_in,
                              void* d_out, int out_size)
{
    const float* x = (const float*)d_in[0];
    const float* y = (const float*)d_in[1];
    const float* t = (const float*)d_in[8];
    const float* l = (const float*)d_in[9];
    const float* a = (const float*)d_in[10];

    float* u1 = (float*)d_out;
    float* u2 = u1 + NPIX;

    static cudaStream_t sB = 0, sC = 0, sD = 0;
    static cudaEvent_t  eF = 0, eMA = 0, eMB = 0, eJB = 0, eJC = 0, eJD = 0;
    static int mode = -1;   // -1 untried, 0 serial fallback, 1 staggered
    if (mode < 0) {
        mode = 1;
        if (cudaStreamCreateWithFlags(&sB, cudaStreamNonBlocking) != cudaSuccess) mode = 0;
        if (mode && cudaStreamCreateWithFlags(&sC, cudaStreamNonBlocking) != cudaSuccess) mode = 0;
        if (mode && cudaStreamCreateWithFlags(&sD, cudaStreamNonBlocking) != cudaSuccess) mode = 0;
        if (mode && (cudaEventCreateWithFlags(&eF,  cudaEventDisableTiming) != cudaSuccess ||
                     cudaEventCreateWithFlags(&eMA, cudaEventDisableTiming) != cudaSuccess ||
                     cudaEventCreateWithFlags(&eMB, cudaEventDisableTiming) != cudaSuccess ||
                     cudaEventCreateWithFlags(&eJB, cudaEventDisableTiming) != cudaSuccess ||
                     cudaEventCreateWithFlags(&eJC, cudaEventDisableTiming) != cudaSuccess ||
                     cudaEventCreateWithFlags(&eJD, cudaEventDisableTiming) != cudaSuccess))
            mode = 0;
    }

    if (mode == 1) {
        // fork
        cudaEventRecord(eF, 0);
        cudaStreamWaitEvent(sB, eF, 0);
        cudaStreamWaitEvent(sC, eF, 0);
        cudaStreamWaitEvent(sD, eF, 0);

        run_quarter(0,  0 * QPIX, x, y, t, l, a, u1, u2, eMA);  // A: q0 (records mid)
        run_quarter(sB, 1 * QPIX, x, y, t, l, a, u1, u2, eMB);  // B: q1 (records mid)
        cudaStreamWaitEvent(sC, eMA, 0);
        run_quarter(sC, 2 * QPIX, x, y, t, l, a, u1, u2, 0);    // C: q2 (staggered)
        cudaStreamWaitEvent(sD, eMB, 0);
        run_quarter(sD, 3 * QPIX, x, y, t, l, a, u1, u2, 0);    // D: q3 (staggered)

        // join everything onto stream 0
        cudaEventRecord(eJB, sB); cudaStreamWaitEvent(0, eJB, 0);
        cudaEventRecord(eJC, sC); cudaStreamWaitEvent(0, eJC, 0);
        cudaEventRecord(eJD, sD); cudaStreamWaitEvent(0, eJD, 0);
    } else {
        for (int q = 0; q < 4; ++q)
            run_quarter(0, q * QPIX, x, y, t, l, a, u1, u2, 0);
    }
}

// round 17
// speedup vs baseline: 1.1096x; 1.1096x over previous
#include <cuda_runtime.h>
#include <cuda_fp16.h>

#define Wd 256
#define Hd 256
#define Bd 64
#define NPIX (Bd*Hd*Wd)
#define QIMG 16
#define QPIX (QIMG*Hd*Wd)   // elements per quarter
#define NVQ  (QPIX/4)       // float4 vectors per quarter (init)
#define NT2  (QPIX/8)       // threads per quarter for 2-row kernels
#define EPSf 1e-12f

// ---- iteration-invariant scratch (fp32) ----
__device__ __align__(16) float g_g2x[NPIX];
__device__ __align__(16) float g_g2y[NPIX];
__device__ __align__(16) float g_rc [NPIX];
// ---- dual state, fp16 packed per pixel: pa = (p11,p21), pb = (p12,p22) ----
__device__ __align__(16) unsigned g_pa[NPIX];
__device__ __align__(16) unsigned g_pb[NPIX];

union F4 { float4 v; float f[4]; };

__device__ __forceinline__ float4 ld4(const float* p) { return *reinterpret_cast<const float4*>(p); }
__device__ __forceinline__ void   st4(float* p, float4 v) { *reinterpret_cast<float4*>(p) = v; }
__device__ __forceinline__ uint4  ldu4(const unsigned* p) { return *reinterpret_cast<const uint4*>(p); }
__device__ __forceinline__ void   stu4(unsigned* p, uint4 v) { *reinterpret_cast<uint4*>(p) = v; }

__device__ __forceinline__ float2 h2f(unsigned w) {
    __half2 h = *reinterpret_cast<__half2*>(&w);
    return __half22float2(h);
}
__device__ __forceinline__ unsigned f2h(float a, float b) {
    __half2 h = __floats2half2_rn(a, b);
    return *reinterpret_cast<unsigned*>(&h);
}
__device__ __forceinline__ unsigned u4get(const uint4& u, int k) {
    return (k == 0) ? u.x : (k == 1) ? u.y : (k == 2) ? u.z : u.w;
}
__device__ __forceinline__ void u4set(uint4& u, int k, unsigned v) {
    if (k == 0) u.x = v; else if (k == 1) u.y = v; else if (k == 2) u.z = v; else u.w = v;
}

// ============================================================================
// Init (per quarter): g2x, g2y (centered grads of y, x boundary), rc, iter-1 u.
// ============================================================================
__global__ void __launch_bounds__(256) k_init(
    const float* __restrict__ x, const float* __restrict__ y,
    const float* __restrict__ tp, const float* __restrict__ lp,
    float* __restrict__ u1, float* __restrict__ u2, int off)
{
    int v = blockIdx.x * blockDim.x + threadIdx.x;
    if (v >= NVQ) return;
    int il = v << 2;
    int idx = il + off;
    int j4 = il & (Wd - 1);
    int i  = (il >> 8) & (Hd - 1);

    float ts  = tp[0];
    float l_t = lp[0] * ts;

    F4 X, Y, Yu, Yd, Xu, Xd;
    X.v = ld4(x + idx);
    Y.v = ld4(y + idx);
    float yl = (j4 > 0)       ? y[idx - 1] : 0.f;
    float yr = (j4 + 4 < Wd)  ? y[idx + 4] : 0.f;
    Yu.v = (i > 0)      ? ld4(y + idx - Wd) : make_float4(0,0,0,0);
    Yd.v = (i < Hd - 1) ? ld4(y + idx + Wd) : make_float4(0,0,0,0);
    Xd.v = (i == 0)      ? ld4(x + idx + Wd) : make_float4(0,0,0,0);
    Xu.v = (i == Hd - 1) ? ld4(x + idx - Wd) : make_float4(0,0,0,0);

    F4 GX, GY, RC, O1, O2;
#pragma unroll
    for (int k = 0; k < 4; k++) {
        int j = j4 + k;
        float gx;
        if (j == 0)            gx = 0.5f * (X.f[1] - X.f[0]);
        else if (j == Wd - 1)  gx = 0.5f * (X.f[3] - X.f[2]);
        else {
            float yn = (k < 3) ? Y.f[k + 1] : yr;
            float yp = (k > 0) ? Y.f[k - 1] : yl;
            gx = 0.5f * (yn - yp);
        }
        float gy;
        if (i == 0)            gy = 0.5f * (Xd.f[k] - X.f[k]);
        else if (i == Hd - 1)  gy = 0.5f * (X.f[k] - Xu.f[k]);
        else                   gy = 0.5f * (Yd.f[k] - Yu.f[k]);

        float rc = Y.f[k] - X.f[k];
        GX.f[k] = gx; GY.f[k] = gy; RC.f[k] = rc;

        float rho  = rc + EPSf;
        float grad = gx * gx + gy * gy + EPSf;
        float lg   = l_t * grad;
        float v1, v2;
        if      (rho < -lg)   { v1 =  l_t * gx; v2 =  l_t * gy; }
        else if (rho >  lg)   { v1 = -l_t * gx; v2 = -l_t * gy; }
        else if (grad > EPSf) { float s = -rho / grad; v1 = s * gx; v2 = s * gy; }
        else                  { v1 = 0.f; v2 = 0.f; }
        O1.f[k] = v1; O2.f[k] = v2;
    }
    st4(g_g2x + idx, GX.v);
    st4(g_g2y + idx, GY.v);
    st4(g_rc  + idx, RC.v);
    st4(u1 + idx, O1.v);
    st4(u2 + idx, O2.v);
}

// shared per-pixel p-update
__device__ __forceinline__ void p_px(
    float uC1, float uR1, float uD1, float uC2, float uR2, float uD2,
    bool hasR, bool hasD, float taut, unsigned pa_old, unsigned pb_old,
    unsigned& pa_new, unsigned& pb_new, bool first)
{
    float u1x = hasR ? (uR1 - uC1) : 0.f;
    float u2x = hasR ? (uR2 - uC2) : 0.f;
    float u1y = hasD ? (uD1 - uC1) : 0.f;
    float u2y = hasD ? (uD2 - uC2) : 0.f;
    float n1 = sqrtf(u1x*u1x + u1y*u1y + EPSf);
    float n2 = sqrtf(u2x*u2x + u2y*u2y + EPSf);
    float f1 = 1.0f / (1.0f + taut * n1);
    float f2 = 1.0f / (1.0f + taut * n2);
    float p11o = 0.f, p21o = 0.f, p12o = 0.f, p22o = 0.f;
    if (!first) {
        float2 a = h2f(pa_old); float2 b = h2f(pb_old);
        p11o = a.x; p21o = a.y; p12o = b.x; p22o = b.y;
    }
    pa_new = f2h((p11o + taut * u1x) * f1, (p21o + taut * u2x) * f2);
    pb_new = f2h((p12o + taut * u1y) * f1, (p22o + taut * u2y) * f2);
}

// ============================================================================
// P update, 2 rows/thread: row0's down-u = row1's center (register reuse).
// Row0 is always an even row (< Hd-1) so its hasD is always true.
// ============================================================================
template <bool FIRST>
__global__ void __launch_bounds__(256) k_update_p(
    const float* __restrict__ tp, const float* __restrict__ ap,
    const float* __restrict__ u1, const float* __restrict__ u2, int off)
{
    int v = blockIdx.x * blockDim.x + threadIdx.x;
    if (v >= NT2) return;
    int img = v >> 13;            // 8192 threads per image
    int rem = v & 8191;
    int rp  = rem >> 6;           // row pair 0..127
    int cv  = rem & 63;           // col vec 0..63
    int j4  = cv << 2;
    int idx0 = off + (img << 16) + (rp << 9) + j4;   // row 2rp
    int idx1 = idx0 + Wd;                            // row 2rp+1

    float taut = ap[0] / tp[0];
    bool hasR = (j4 + 4 < Wd);

    // u centers for both rows
    F4 U1a, U2a, U1b, U2b;
    U1a.v = ld4(u1 + idx0); U2a.v = ld4(u2 + idx0);
    U1b.v = ld4(u1 + idx1); U2b.v = ld4(u2 + idx1);
    float u1r0 = hasR ? u1[idx0 + 4] : 0.f;
    float u2r0 = hasR ? u2[idx0 + 4] : 0.f;
    float u1r1 = hasR ? u1[idx1 + 4] : 0.f;
    float u2r1 = hasR ? u2[idx1 + 4] : 0.f;
    // row1's down (row 2rp+2)
    bool hasd1 = (rp < 127);
    F4 U1c, U2c;
    U1c.v = hasd1 ? ld4(u1 + idx1 + Wd) : make_float4(0,0,0,0);
    U2c.v = hasd1 ? ld4(u2 + idx1 + Wd) : make_float4(0,0,0,0);

    uint4 PA0 = make_uint4(0,0,0,0), PB0 = PA0, PA1 = PA0, PB1 = PA0;
    if (!FIRST) {
        PA0 = ldu4(g_pa + idx0); PB0 = ldu4(g_pb + idx0);
        PA1 = ldu4(g_pa + idx1); PB1 = ldu4(g_pb + idx1);
    }

    // row0: down = row1 center (always valid)
    uint4 OA0, OB0;
#pragma unroll
    for (int k = 0; k < 4; k++) {
        float uR1 = (k < 3) ? U1a.f[k+1] : u1r0;
        float uR2 = (k < 3) ? U2a.f[k+1] : u2r0;
        unsigned na, nb;
        p_px(U1a.f[k], uR1, U1b.f[k], U2a.f[k], uR2, U2b.f[k],
             (j4 + k < Wd - 1), true, taut,
             u4get(PA0, k), u4get(PB0, k), na, nb, FIRST);
        u4set(OA0, k, na); u4set(OB0, k, nb);
    }
    stu4(g_pa + idx0, OA0);
    stu4(g_pb + idx0, OB0);

    // row1: down = row 2rp+2 (loaded)
    uint4 OA1, OB1;
#pragma unroll
    for (int k = 0; k < 4; k++) {
        float uR1 = (k < 3) ? U1b.f[k+1] : u1r1;
        float uR2 = (k < 3) ? U2b.f[k+1] : u2r1;
        unsigned na, nb;
        p_px(U1b.f[k], uR1, U1c.f[k], U2b.f[k], uR2, U2c.f[k],
             (j4 + k < Wd - 1), hasd1, taut,
             u4get(PA1, k), u4get(PB1, k), na, nb, FIRST);
        u4set(OA1, k, na); u4set(OB1, k, nb);
    }
    stu4(g_pa + idx1, OA1);
    stu4(g_pb + idx1, OB1);
}

// shared per-vec u-update (one row of 4 px)
__device__ __forceinline__ void u_vec4(
    const F4& U1, const F4& U2, const F4& GX, const F4& GY, const F4& RC,
    const uint4& PA, const uint4& PB, const uint4& PBu,
    float p11l, float p21l, int j4, bool i0, bool has_up,
    float ts, float l_t, F4& O1, F4& O2)
{
#pragma unroll
    for (int k = 0; k < 4; k++) {
        int j = j4 + k;
        float2 a  = h2f(u4get(PA, k));
        float2 b  = h2f(u4get(PB, k));
        float2 bu = h2f(u4get(PBu, k));

        float lft11, lft21;
        if (k > 0) {
            float2 al = h2f(u4get(PA, k - 1));
            lft11 = al.x; lft21 = al.y;
        } else { lft11 = p11l; lft21 = p21l; }

        float dx1 = (j == 0) ? a.x : (a.x - lft11);
        float dx2 = (j == 0) ? a.y : (a.y - lft21);
        float dy1 = has_up ? (b.x - bu.x) : b.x;
        float dy2 = has_up ? (b.y - bu.y) : b.y;
        if (i0) { dy1 = b.x; dy2 = b.y; }

        float gx = GX.f[k], gy = GY.f[k];
        float rho  = RC.f[k] + gx * U1.f[k] + gy * U2.f[k] + EPSf;
        float grad = gx * gx + gy * gy + EPSf;
        float lg   = l_t * grad;
        float v1, v2;
        if      (rho < -lg)   { v1 =  l_t * gx; v2 =  l_t * gy; }
        else if (rho >  lg)   { v1 = -l_t * gx; v2 = -l_t * gy; }
        else if (grad > EPSf) { float s = -rho / grad; v1 = s * gx; v2 = s * gy; }
        else                  { v1 = 0.f; v2 = 0.f; }

        O1.f[k] = U1.f[k] + v1 + ts * (dx1 + dy1);
        O2.f[k] = U2.f[k] + v2 + ts * (dx2 + dy2);
    }
}

// ============================================================================
// U update, 2 rows/thread: row1's up-pb = row0's pb (register reuse).
// ============================================================================
__global__ void __launch_bounds__(256) k_update_u(
    const float* __restrict__ tp, const float* __restrict__ lp,
    float* __restrict__ u1, float* __restrict__ u2, int off)
{
    int v = blockIdx.x * blockDim.x + threadIdx.x;
    if (v >= NT2) return;
    int img = v >> 13;
    int rem = v & 8191;
    int rp  = rem >> 6;
    int cv  = rem & 63;
    int j4  = cv << 2;
    int idx0 = off + (img << 16) + (rp << 9) + j4;
    int idx1 = idx0 + Wd;

    float ts  = tp[0];
    float l_t = lp[0] * ts;
    bool hasL = (j4 > 0);
    bool row0_top = (rp == 0);

    // ---- row0 ----
    {
        F4 U1, U2, GX, GY, RC;
        U1.v = ld4(u1 + idx0); U2.v = ld4(u2 + idx0);
        GX.v = ld4(g_g2x + idx0); GY.v = ld4(g_g2y + idx0); RC.v = ld4(g_rc + idx0);
        uint4 PA0 = ldu4(g_pa + idx0);
        uint4 PB0 = ldu4(g_pb + idx0);
        uint4 PBu = row0_top ? make_uint4(0,0,0,0) : ldu4(g_pb + idx0 - Wd);
        float p11l = 0.f, p21l = 0.f;
        if (hasL) { float2 a = h2f(g_pa[idx0 - 1]); p11l = a.x; p21l = a.y; }

        F4 O1, O2;
        u_vec4(U1, U2, GX, GY, RC, PA0, PB0, PBu, p11l, p21l,
               j4, row0_top, !row0_top, ts, l_t, O1, O2);
        st4(u1 + idx0, O1.v);
        st4(u2 + idx0, O2.v);

        // ---- row1 (up = row0's pb, carried in PB0) ----
        F4 V1, V2, HX, HY, SC;
        V1.v = ld4(u1 + idx1); V2.v = ld4(u2 + idx1);
        HX.v = ld4(g_g2x + idx1); HY.v = ld4(g_g2y + idx1); SC.v = ld4(g_rc + idx1);
        uint4 PA1 = ldu4(g_pa + idx1);
        uint4 PB1 = ldu4(g_pb + idx1);
        float q11l = 0.f, q21l = 0.f;
        if (hasL) { float2 a = h2f(g_pa[idx1 - 1]); q11l = a.x; q21l = a.y; }

        F4 Q1, Q2;
        u_vec4(V1, V2, HX, HY, SC, PA1, PB1, PB0, q11l, q21l,
               j4, false, true, ts, l_t, Q1, Q2);
        st4(u1 + idx1, Q1.v);
        st4(u2 + idx1, Q2.v);
    }
}

// ============================================================================
// Host: one quarter-pipeline on a stream (R15 schedule, no stagger).
// ============================================================================
static void run_quarter(cudaStream_t s, int off,
                        const float* x, const float* y,
                        const float* t, const float* l, const float* a,
                        float* u1, float* u2)
{
    const int threads = 256;
    const int blocksI = (NVQ + threads - 1) / threads;
    const int blocks2 = (NT2 + threads - 1) / threads;
    k_init<<<blocksI, threads, 0, s>>>(x, y, t, l, u1, u2, off);
    k_update_p<true><<<blocks2, threads, 0, s>>>(t, a, u1, u2, off);
    for (int it = 0; it < 9; ++it) {
        k_update_u<<<blocks2, threads, 0, s>>>(t, l, u1, u2, off);
        if (it < 8)
            k_update_p<false><<<blocks2, threads, 0, s>>>(t, a, u1, u2, off);
    }
}

// ============================================================================
// Launch: R15's proven two-stream schedule. A: q0,q2 ; B: q1,q3.
// Concurrent WS = 2 x 28MB = 56MB, L2-resident.
// ============================================================================
extern "C" void kernel_launch(void* const* d_in, const int* in_sizes, int n_in,
                              void* d_out, int out_size)
{
    const float* x = (const float*)d_in[0];
    const float* y = (const float*)d_in[1];
    const float* t = (const float*)d_in[8];
    const float* l = (const float*)d_in[9];
    const float* a = (const float*)d_in[10];

    float* u1 = (float*)d_out;
    float* u2 = u1 + NPIX;

    static cudaStream_t s1 = 0;
    static cudaEvent_t  eF = 0, eJ = 0;
    static bool tried = false;
    if (!tried) {
        tried = true;
        if (cudaStreamCreateWithFlags(&s1, cudaStreamNonBlocking) != cudaSuccess) s1 = 0;
        if (s1) {
            if (cudaEventCreateWithFlags(&eF, cudaEventDisableTiming) != cudaSuccess ||
                cudaEventCreateWithFlags(&eJ, cudaEventDisableTiming) != cudaSuccess) {
                s1 = 0;
            }
        }
    }

    if (s1) {
        cudaEventRecord(eF, 0);
        cudaStreamWaitEvent(s1, eF, 0);
        run_quarter(0,  0 * QPIX, x, y, t, l, a, u1, u2);
        run_quarter(s1, 1 * QPIX, x, y, t, l, a, u1, u2);
        run_quarter(0,  2 * QPIX, x, y, t, l, a, u1, u2);
        run_quarter(s1, 3 * QPIX, x, y, t, l, a, u1, u2);
        cudaEventRecord(eJ, s1);
        cudaStreamWaitEvent(0, eJ, 0);
    } else {
        for (int q = 0; q < 4; ++q)
            run_quarter(0, q * QPIX, x, y, t, l, a, u1, u2);
    }
}